// round 10
// baseline (speedup 1.0000x reference)
#include <cuda_runtime.h>

#define NB    128
#define CIN   8
#define HIN   128
#define WIN   128
#define COUT  64
#define HO    126
#define WO    126
#define PHN   31
#define PWN   31
#define NG    16
#define CPG   4

typedef unsigned long long u64;

__device__ float  g_sext[(size_t)NB * COUT * PHN * PWN];   // max of sign-adjusted conv over window
__device__ float2 g_partial[32 * NB * NG];
__device__ float2 g_stats[NB * NG];

// ---- packed f32x2 helpers (sm_100+) ----
__device__ __forceinline__ u64 pk2(float lo, float hi) {
    u64 r; asm("mov.b64 %0, {%1, %2};" : "=l"(r) : "f"(lo), "f"(hi)); return r;
}
__device__ __forceinline__ void upk2(float& lo, float& hi, u64 p) {
    asm("mov.b64 {%0, %1}, %2;" : "=f"(lo), "=f"(hi) : "l"(p));
}
__device__ __forceinline__ void ffma2(u64& d, u64 a, u64 b) {
    asm("fma.rn.f32x2 %0, %1, %2, %0;" : "+l"(d) : "l"(a), "l"(b));
}
__device__ __forceinline__ void fadd2(u64& d, u64 a) {
    asm("add.rn.f32x2 %0, %1, %0;" : "+l"(d) : "l"(a));
}

// ---------------------------------------------------------------------------
// Pass 1: conv + bias; per-window sign-adjusted max; per-(b,g) partial stats.
// Grid: (32 row-groups, 128 batches, 2 channel-halves), block = 256.
// Thread t: wx = t&31 (4-col window), cb = t>>5 -> channels z*32+cb*4..+3.
// Warp (fixed cb) owns exactly GroupNorm group g = z*8+cb.
// f32x2 packed over CHANNEL pairs. 2-row output blocking with input-row
// streaming: each x row loaded from smem ONCE per cin per row-pair; tap-set
// registers reused across the h-steps (halves crossbar traffic vs 1-row).
// ---------------------------------------------------------------------------
__global__ __launch_bounds__(256, 3) void conv_pass1(const float* __restrict__ x,
                                                     const float* __restrict__ w,
                                                     const float* __restrict__ bias,
                                                     const float* __restrict__ gnw,
                                                     const float* __restrict__ scale)
{
    const int pr = blockIdx.x;          // 0..31
    const int b  = blockIdx.y;
    const int z  = blockIdx.z;          // channel half
    const int t  = threadIdx.x;

    __shared__ float xs[CIN][6][132];   // 6 input rows, 128 cols + 4 zero pad
    __shared__ float wsm[72][32];       // [cin*9+ky*3+kx][cl]  scalar
    __shared__ float bsm[32];
    __shared__ float sgsm[32];          // +1 / -1 per channel

    // weights for this half: global layout [co][cin][ky][kx]
    for (int i = t; i < 72 * 32; i += 256) {
        int cl = i & 31, k = i >> 5;
        wsm[k][cl] = w[(z * 32 + cl) * 72 + k];
    }
    if (t < 32) {
        bsm[t]  = bias[z * 32 + t];
        sgsm[t] = (gnw[z * 32 + t] * scale[z * 32 + t] < 0.f) ? -1.f : 1.f;
    }

    const int h0 = pr * 4;
    for (int i = t; i < CIN * 6 * 32; i += 256) {
        int c4  = i & 31;
        int rr  = (i >> 5) % 6;
        int cin = i / (6 * 32);
        int h   = h0 + rr;
        float4 v = make_float4(0.f, 0.f, 0.f, 0.f);
        if (h < HIN)
            v = *(const float4*)&x[(((size_t)b * CIN + cin) * HIN + h) * WIN + c4 * 4];
        *(float4*)&xs[cin][rr][c4 * 4] = v;
    }
    if (t < CIN * 6) {
        int rr = t % 6, cin = t / 6;
        *(float4*)&xs[cin][rr][128] = make_float4(0.f, 0.f, 0.f, 0.f);
    }
    __syncthreads();

    const int wx   = t & 31;
    const int cb   = t >> 5;
    const int col0 = wx * 4;
    const int R    = (pr == 31) ? 2 : 4;

    float wext[4];
#pragma unroll
    for (int j = 0; j < 4; j++) wext[j] = -1e30f;
    u64 s2 = 0ULL, q2 = 0ULL;           // packed (even-ch, odd-ch) stats

#pragma unroll 1
    for (int rr = 0; rr < R; rr += 2) {
        u64 acc[2][2][4];               // [output row][channel pair][column]
#pragma unroll
        for (int r2 = 0; r2 < 2; r2++)
#pragma unroll
            for (int p = 0; p < 2; p++)
#pragma unroll
                for (int c = 0; c < 4; c++) acc[r2][p][c] = 0ULL;

#pragma unroll 1
        for (int cin = 0; cin < CIN; cin++) {
            ulonglong2 W[3][3];         // [ky][tap]; each loaded once per cin
#pragma unroll
            for (int h = 0; h < 4; h++) {
                // load input row rr+h once; pack (x,x) duplicates
                const float* xr = &xs[cin][rr + h][col0];
                float4 xa = *(const float4*)xr;
                float2 xb = *(const float2*)(xr + 4);
                u64 xd[6];
                xd[0] = pk2(xa.x, xa.x); xd[1] = pk2(xa.y, xa.y);
                xd[2] = pk2(xa.z, xa.z); xd[3] = pk2(xa.w, xa.w);
                xd[4] = pk2(xb.x, xb.x); xd[5] = pk2(xb.y, xb.y);

                if (h <= 2) {           // fetch tap-set ky=h (first use)
#pragma unroll
                    for (int tp = 0; tp < 3; tp++)
                        W[h][tp] = *(const ulonglong2*)&wsm[cin * 9 + h * 3 + tp][cb * 4];
                    // output row 0, ky = h
#pragma unroll
                    for (int c = 0; c < 4; c++) {
                        ffma2(acc[0][0][c], W[h][0].x, xd[c + 0]);
                        ffma2(acc[0][0][c], W[h][1].x, xd[c + 1]);
                        ffma2(acc[0][0][c], W[h][2].x, xd[c + 2]);
                        ffma2(acc[0][1][c], W[h][0].y, xd[c + 0]);
                        ffma2(acc[0][1][c], W[h][1].y, xd[c + 1]);
                        ffma2(acc[0][1][c], W[h][2].y, xd[c + 2]);
                    }
                }
                if (h >= 1) {           // output row 1, ky = h-1 (reuse tap-set)
#pragma unroll
                    for (int c = 0; c < 4; c++) {
                        ffma2(acc[1][0][c], W[h - 1][0].x, xd[c + 0]);
                        ffma2(acc[1][0][c], W[h - 1][1].x, xd[c + 1]);
                        ffma2(acc[1][0][c], W[h - 1][2].x, xd[c + 2]);
                        ffma2(acc[1][1][c], W[h - 1][0].y, xd[c + 0]);
                        ffma2(acc[1][1][c], W[h - 1][1].y, xd[c + 1]);
                        ffma2(acc[1][1][c], W[h - 1][2].y, xd[c + 2]);
                    }
                }
            }
        }

        // epilogue: bias, stats, sign-adjusted window max (both rows)
        u64 bp[2];
        bp[0] = *(const u64*)&bsm[cb * 4 + 0];
        bp[1] = *(const u64*)&bsm[cb * 4 + 2];
        float sg0 = sgsm[cb * 4 + 0], sg1 = sgsm[cb * 4 + 1];
        float sg2 = sgsm[cb * 4 + 2], sg3 = sgsm[cb * 4 + 3];
#pragma unroll
        for (int r2 = 0; r2 < 2; r2++) {
#pragma unroll
            for (int p = 0; p < 2; p++) {
                float sgl = p ? sg2 : sg0;
                float sgh = p ? sg3 : sg1;
#pragma unroll
                for (int c = 0; c < 4; c++) {
                    u64 a = acc[r2][p][c];
                    fadd2(a, bp[p]);
                    if (wx < 31 || c < 2) {     // real column (<126)
                        fadd2(s2, a);
                        ffma2(q2, a, a);
                    }
                    if (wx < 31) {              // real pooled window
                        float v0, v1;
                        upk2(v0, v1, a);
                        int j0 = 2 * p, j1 = 2 * p + 1;
                        wext[j0] = fmaxf(wext[j0], sgl * v0);
                        wext[j1] = fmaxf(wext[j1], sgh * v1);
                    }
                }
            }
        }
    }

    // pooled window sign-adjusted max
    if (pr < 31 && wx < 31) {
#pragma unroll
        for (int j = 0; j < 4; j++) {
            int co = z * 32 + cb * 4 + j;
            size_t o = (((size_t)b * COUT + co) * PHN + pr) * PWN + wx;
            g_sext[o] = wext[j];
        }
    }

    // warp-level stats reduction; warp cb exclusively owns group z*8+cb
    float sl, sh, ql, qh;
    upk2(sl, sh, s2); upk2(ql, qh, q2);
    float s = sl + sh, q = ql + qh;
#pragma unroll
    for (int o = 16; o > 0; o >>= 1) {
        s += __shfl_down_sync(0xffffffffu, s, o);
        q += __shfl_down_sync(0xffffffffu, q, o);
    }
    if (wx == 0)
        g_partial[(pr * NB + b) * NG + z * 8 + cb] = make_float2(s, q);
}

// ---------------------------------------------------------------------------
// Pass 2: fold 32 row-group partials into mean/rstd per (b, g).
// ---------------------------------------------------------------------------
__global__ void stats_pass2()
{
    int idx = blockIdx.x * 256 + threadIdx.x;   // b*16+g
    if (idx >= NB * NG) return;
    float s = 0.f, q = 0.f;
    for (int pr = 0; pr < 32; pr++) {
        float2 p = g_partial[pr * (NB * NG) + idx];
        s += p.x; q += p.y;
    }
    const float inv = 1.f / (float)(CPG * HO * WO);
    float mean = s * inv;
    float var  = q * inv - mean * mean;
    g_stats[idx] = make_float2(mean, rsqrtf(var + 1e-5f));
}

// ---------------------------------------------------------------------------
// Pass 3: v = |A| * ext + B, clamp.  (ext = max of sign(A)-adjusted conv)
// ---------------------------------------------------------------------------
__global__ void apply_pass3(const float* __restrict__ gnw,
                            const float* __restrict__ gnb,
                            const float* __restrict__ scale,
                            float* __restrict__ out, int n)
{
    int idx = blockIdx.x * 256 + threadIdx.x;
    if (idx >= n) return;
    int tmp = idx / PWN;
    tmp /= PHN;
    int c = tmp % COUT;
    int b = tmp / COUT;

    float2 st = g_stats[b * NG + (c >> 2)];
    float gw = gnw[c], sc = scale[c];
    float A  = st.y * gw * sc;
    float Bt = (gnb[c] - st.x * st.y * gw) * sc;

    float v = fmaf(fabsf(A), g_sext[idx], Bt);
    out[idx] = fminf(fmaxf(v, 0.f), 1.f);
}

// ---------------------------------------------------------------------------
extern "C" void kernel_launch(void* const* d_in, const int* in_sizes, int n_in,
                              void* d_out, int out_size)
{
    const float* x     = (const float*)d_in[0];
    const float* w     = (const float*)d_in[1];
    const float* bias  = (const float*)d_in[2];
    const float* gnw   = (const float*)d_in[3];
    const float* gnb   = (const float*)d_in[4];
    const float* scale = (const float*)d_in[5];
    float* out = (float*)d_out;

    dim3 g1(32, NB, 2);
    conv_pass1<<<g1, 256>>>(x, w, bias, gnw, scale);
    stats_pass2<<<(NB * NG + 255) / 256, 256>>>();
    int n = NB * COUT * PHN * PWN;
    apply_pass3<<<(n + 255) / 256, 256>>>(gnw, gnb, scale, out, n);
}

// round 11
// speedup vs baseline: 1.1601x; 1.1601x over previous
#include <cuda_runtime.h>

#define NB    128
#define CIN   8
#define HIN   128
#define WIN   128
#define COUT  64
#define HO    126
#define WO    126
#define PHN   31
#define PWN   31
#define NG    16
#define CPG   4

__device__ float  g_sext[(size_t)NB * COUT * PHN * PWN];
__device__ float2 g_partial[32 * NB * NG];
__device__ float2 g_stats[NB * NG];

// ---- smem layout (dynamic, bytes) ----
#define XS2_OFF   0         // float2[8][6][144]  (hi,lo) x tile, row stride 144
#define WFH_OFF   55296     // float4[9*4*32]     A-frag hi
#define WFL_OFF   73728     // float4[9*4*32]     A-frag lo
#define KOFF_OFF  92160     // int[72]
#define BSM_OFF   92448     // float[64]
#define SGS_OFF   92704     // float[64]
#define SRED_OFF  92960     // float2[64][8]
#define SMEM_TOTAL 97056

#define XROW 144            // padded row stride (float2 units); 144*8B = 9*128B aligned

__device__ __forceinline__ unsigned f2tf(float f) {
    unsigned u; asm("cvt.rna.tf32.f32 %0, %1;" : "=r"(u) : "f"(f)); return u;
}
__device__ __forceinline__ void mma8(float* d, const unsigned* a, unsigned b0, unsigned b1) {
    asm("mma.sync.aligned.m16n8k8.row.col.f32.tf32.tf32.f32 "
        "{%0,%1,%2,%3}, {%4,%5,%6,%7}, {%8,%9}, {%0,%1,%2,%3};"
        : "+f"(d[0]), "+f"(d[1]), "+f"(d[2]), "+f"(d[3])
        : "r"(a[0]), "r"(a[1]), "r"(a[2]), "r"(a[3]), "r"(b0), "r"(b1));
}

// ---------------------------------------------------------------------------
// Pass 1: tf32 tensor-core conv (split hi/lo, 3-term) + bias + window max +
// group stats. Grid (32 rowgroups, 128 batch), block 256 = 8 warps.
// Warp wid covers cols wid*16..wid*16+15 (2 n-tiles), all 64 couts (4 m-tiles).
// Rows r=0..3 sequential. k = cin*9+ky*3+kx, 9 k-steps of 8.
// ---------------------------------------------------------------------------
__global__ __launch_bounds__(256, 2) void conv_pass1(const float* __restrict__ x,
                                                     const float* __restrict__ w,
                                                     const float* __restrict__ bias,
                                                     const float* __restrict__ gnw,
                                                     const float* __restrict__ scale)
{
    extern __shared__ __align__(16) char smem[];
    float2* xs2   = (float2*)(smem + XS2_OFF);
    float4* wfh   = (float4*)(smem + WFH_OFF);
    float4* wfl   = (float4*)(smem + WFL_OFF);
    int*    koffq = (int*)   (smem + KOFF_OFF);
    float*  bsm   = (float*) (smem + BSM_OFF);
    float*  sgsm  = (float*) (smem + SGS_OFF);
    float2* sred  = (float2*)(smem + SRED_OFF);

    const int pr = blockIdx.x;
    const int b  = blockIdx.y;
    const int t  = threadIdx.x;

    // ---- setup: weight fragments (hi/lo) ----
    for (int e = t; e < 1152; e += 256) {          // e = (ks*4+mt)*32 + lane
        int lane = e & 31, mt = (e >> 5) & 3, ks = e >> 7;
        int co0 = mt * 16 + (lane >> 2);
        int k0  = ks * 8 + (lane & 3);
        float f0 = w[co0 * 72 + k0];
        float f1 = w[(co0 + 8) * 72 + k0];
        float f2 = w[co0 * 72 + k0 + 4];
        float f3 = w[(co0 + 8) * 72 + k0 + 4];
        unsigned h0 = f2tf(f0), h1 = f2tf(f1), h2 = f2tf(f2), h3 = f2tf(f3);
        wfh[e] = make_float4(__uint_as_float(h0), __uint_as_float(h1),
                             __uint_as_float(h2), __uint_as_float(h3));
        wfl[e] = make_float4(
            __uint_as_float(f2tf(f0 - __uint_as_float(h0))),
            __uint_as_float(f2tf(f1 - __uint_as_float(h1))),
            __uint_as_float(f2tf(f2 - __uint_as_float(h2))),
            __uint_as_float(f2tf(f3 - __uint_as_float(h3))));
    }
    if (t < 72) {
        int cin = t / 9, rem = t % 9;
        koffq[t] = cin * (6 * XROW) + (rem / 3) * XROW + (rem % 3);
    }
    if (t < 64) {
        bsm[t]  = bias[t];
        sgsm[t] = (gnw[t] * scale[t] < 0.f) ? -1.f : 1.f;
    }

    // ---- setup: x tile as (hi, lo) float2, rows h0..h0+5, cols 0..127 + pad ----
    const int h0 = pr * 4;
    for (int i = t; i < CIN * 6 * 32; i += 256) {
        int c4  = i & 31;
        int rr  = (i >> 5) % 6;
        int cin = i / 192;
        int h   = h0 + rr;
        float4 v = make_float4(0.f, 0.f, 0.f, 0.f);
        if (h < HIN)
            v = *(const float4*)&x[(((size_t)b * CIN + cin) * HIN + h) * WIN + c4 * 4];
        int base = cin * (6 * XROW) + rr * XROW + c4 * 4;
        const float* vp = (const float*)&v;
#pragma unroll
        for (int e = 0; e < 4; e++) {
            unsigned hb = f2tf(vp[e]);
            float hf = __uint_as_float(hb);
            xs2[base + e] = make_float2(hf, __uint_as_float(f2tf(vp[e] - hf)));
        }
    }
    if (t < CIN * 6) {                              // zero pad cols 128..143
        int rr = t % 6, cin = t / 6;
        int base = cin * (6 * XROW) + rr * XROW + 128;
#pragma unroll
        for (int e = 0; e < 16; e++) xs2[base + e] = make_float2(0.f, 0.f);
    }
    __syncthreads();

    const int lane = t & 31, wid = t >> 5;
    const int g4 = lane >> 2, t4 = lane & 3;
    const int colbase = wid * 16;
    const int R = (pr == 31) ? 2 : 4;

    float s8[8], q8[8], wmax[8][2];
#pragma unroll
    for (int i = 0; i < 8; i++) {
        s8[i] = 0.f; q8[i] = 0.f;
        wmax[i][0] = -1e30f; wmax[i][1] = -1e30f;
    }

#pragma unroll 1
    for (int r = 0; r < R; r++) {
        float acc[4][2][4];
#pragma unroll
        for (int mt = 0; mt < 4; mt++)
#pragma unroll
            for (int nt = 0; nt < 2; nt++)
#pragma unroll
                for (int e = 0; e < 4; e++) acc[mt][nt][e] = 0.f;

#pragma unroll 1
        for (int ks = 0; ks < 9; ks++) {
            int kk = ks * 8 + t4;
            int o0 = koffq[kk], o1 = koffq[kk + 4];
            int rb = r * XROW + colbase + g4;
            float2 v00 = xs2[o0 + rb],     v10 = xs2[o1 + rb];
            float2 v01 = xs2[o0 + rb + 8], v11 = xs2[o1 + rb + 8];
            unsigned bh[2][2] = {{__float_as_uint(v00.x), __float_as_uint(v10.x)},
                                 {__float_as_uint(v01.x), __float_as_uint(v11.x)}};
            unsigned bl[2][2] = {{__float_as_uint(v00.y), __float_as_uint(v10.y)},
                                 {__float_as_uint(v01.y), __float_as_uint(v11.y)}};
#pragma unroll
            for (int mt = 0; mt < 4; mt++) {
                float4 ah4 = wfh[(ks * 4 + mt) * 32 + lane];
                float4 al4 = wfl[(ks * 4 + mt) * 32 + lane];
                unsigned ah[4] = {__float_as_uint(ah4.x), __float_as_uint(ah4.y),
                                  __float_as_uint(ah4.z), __float_as_uint(ah4.w)};
                unsigned al[4] = {__float_as_uint(al4.x), __float_as_uint(al4.y),
                                  __float_as_uint(al4.z), __float_as_uint(al4.w)};
#pragma unroll
                for (int nt = 0; nt < 2; nt++) {
                    mma8(acc[mt][nt], ah, bh[nt][0], bh[nt][1]);
                    mma8(acc[mt][nt], ah, bl[nt][0], bl[nt][1]);
                    mma8(acc[mt][nt], al, bh[nt][0], bh[nt][1]);
                }
            }
        }

        // epilogue row r: bias, stats, sign-adjusted window max
#pragma unroll
        for (int mt = 0; mt < 4; mt++) {
#pragma unroll
            for (int nt = 0; nt < 2; nt++) {
                int col0 = colbase + nt * 8 + 2 * t4;
                bool ok0 = (col0 < 126), ok1 = (col0 + 1 < 126);
#pragma unroll
                for (int cr = 0; cr < 2; cr++) {
                    int co = mt * 16 + g4 + cr * 8;
                    float bb = bsm[co], sg = sgsm[co];
                    float va = acc[mt][nt][cr * 2 + 0] + bb;
                    float vb = acc[mt][nt][cr * 2 + 1] + bb;
                    int si = mt * 2 + cr;
                    if (ok0) { s8[si] += va; q8[si] += va * va; }
                    if (ok1) { s8[si] += vb; q8[si] += vb * vb; }
                    float pm = fmaxf(sg * va, sg * vb);
                    float po = __shfl_xor_sync(0xffffffffu, pm, 1);
                    pm = fmaxf(pm, po);
                    wmax[si][nt] = fmaxf(wmax[si][nt], pm);
                }
            }
        }
    }

    // pooled window writes (windows are 4 cols x 4 rows; this block = pool row pr)
    if (pr < 31 && (lane & 1) == 0) {
#pragma unroll
        for (int mt = 0; mt < 4; mt++)
#pragma unroll
            for (int cr = 0; cr < 2; cr++)
#pragma unroll
                for (int nt = 0; nt < 2; nt++) {
                    int pw = wid * 4 + nt * 2 + (t4 >> 1);
                    if (pw < 31) {
                        int co = mt * 16 + g4 + cr * 8;
                        size_t o = (((size_t)b * COUT + co) * PHN + pr) * PWN + pw;
                        g_sext[o] = wmax[mt * 2 + cr][nt];
                    }
                }
    }

    // stats: reduce over t4 lanes (same co), stage per (co, warp), fold
#pragma unroll
    for (int i = 0; i < 8; i++) {
        s8[i] += __shfl_xor_sync(0xffffffffu, s8[i], 1);
        s8[i] += __shfl_xor_sync(0xffffffffu, s8[i], 2);
        q8[i] += __shfl_xor_sync(0xffffffffu, q8[i], 1);
        q8[i] += __shfl_xor_sync(0xffffffffu, q8[i], 2);
    }
    if (t4 == 0) {
#pragma unroll
        for (int mt = 0; mt < 4; mt++)
#pragma unroll
            for (int cr = 0; cr < 2; cr++) {
                int co = mt * 16 + g4 + cr * 8;
                sred[co * 8 + wid] = make_float2(s8[mt * 2 + cr], q8[mt * 2 + cr]);
            }
    }
    __syncthreads();
    if (t < NG) {
        float s = 0.f, q = 0.f;
        for (int c = 0; c < 4; c++)
            for (int w8 = 0; w8 < 8; w8++) {
                float2 p = sred[(t * 4 + c) * 8 + w8];
                s += p.x; q += p.y;
            }
        g_partial[(pr * NB + b) * NG + t] = make_float2(s, q);
    }
}

// ---------------------------------------------------------------------------
__global__ void stats_pass2()
{
    int idx = blockIdx.x * 256 + threadIdx.x;
    if (idx >= NB * NG) return;
    float s = 0.f, q = 0.f;
    for (int pr = 0; pr < 32; pr++) {
        float2 p = g_partial[pr * (NB * NG) + idx];
        s += p.x; q += p.y;
    }
    const float inv = 1.f / (float)(CPG * HO * WO);
    float mean = s * inv;
    float var  = q * inv - mean * mean;
    g_stats[idx] = make_float2(mean, rsqrtf(var + 1e-5f));
}

// ---------------------------------------------------------------------------
__global__ void apply_pass3(const float* __restrict__ gnw,
                            const float* __restrict__ gnb,
                            const float* __restrict__ scale,
                            float* __restrict__ out, int n)
{
    int idx = blockIdx.x * 256 + threadIdx.x;
    if (idx >= n) return;
    int tmp = idx / PWN;
    tmp /= PHN;
    int c = tmp % COUT;
    int b = tmp / COUT;

    float2 st = g_stats[b * NG + (c >> 2)];
    float gw = gnw[c], sc = scale[c];
    float A  = st.y * gw * sc;
    float Bt = (gnb[c] - st.x * st.y * gw) * sc;

    float v = fmaf(fabsf(A), g_sext[idx], Bt);
    out[idx] = fminf(fmaxf(v, 0.f), 1.f);
}

// ---------------------------------------------------------------------------
extern "C" void kernel_launch(void* const* d_in, const int* in_sizes, int n_in,
                              void* d_out, int out_size)
{
    const float* x     = (const float*)d_in[0];
    const float* w     = (const float*)d_in[1];
    const float* bias  = (const float*)d_in[2];
    const float* gnw   = (const float*)d_in[3];
    const float* gnb   = (const float*)d_in[4];
    const float* scale = (const float*)d_in[5];
    float* out = (float*)d_out;

    cudaFuncSetAttribute(conv_pass1, cudaFuncAttributeMaxDynamicSharedMemorySize,
                         SMEM_TOTAL);
    dim3 g1(32, NB);
    conv_pass1<<<g1, 256, SMEM_TOTAL>>>(x, w, bias, gnw, scale);
    stats_pass2<<<(NB * NG + 255) / 256, 256>>>();
    int n = NB * COUT * PHN * PWN;
    apply_pass3<<<(n + 255) / 256, 256>>>(gnw, gnb, scale, out, n);
}

// round 13
// speedup vs baseline: 1.3894x; 1.1977x over previous
#include <cuda_runtime.h>

#define NB    128
#define CIN   8
#define HIN   128
#define WIN   128
#define COUT  64
#define HO    126
#define WO    126
#define PHN   31
#define PWN   31
#define NG    16
#define CPG   4

__device__ float  g_sext[(size_t)NB * COUT * PHN * PWN];
__device__ float2 g_partial[32 * NB * NG];
__device__ float2 g_stats[NB * NG];

// ---- smem layout (bytes). XROW=132 floats -> cin stride 792 ≡ 24 (mod 32)
// banks for B-frag lanes: {g4, 24+g4, 16+g4, 8+g4} -> conflict-free LDS.32.
#define XROW      132
#define CINSTRIDE 792              // 6*132 floats
#define XHI_OFF   0                // float[8*792] = 25344 B
#define XLO_OFF   25344            // float[8*792]
#define WFH_OFF   50688            // float4[9*4*32] = 18432 B
#define WFL_OFF   69120            // float4[9*4*32]
#define BSM_OFF   87552            // float[64]
#define SGS_OFF   87808            // float[64]
#define SRED_OFF  88064            // float2[64*8] = 4096 B
#define SMEM_TOTAL 92160           // (fixed: sred is 4096 B, not 2048)

__device__ __forceinline__ unsigned f2tf(float f) {
    unsigned u; asm("cvt.rna.tf32.f32 %0, %1;" : "=r"(u) : "f"(f)); return u;
}
__device__ __forceinline__ void mma8(float* d, const unsigned* a, unsigned b0, unsigned b1) {
    asm("mma.sync.aligned.m16n8k8.row.col.f32.tf32.tf32.f32 "
        "{%0,%1,%2,%3}, {%4,%5,%6,%7}, {%8,%9}, {%0,%1,%2,%3};"
        : "+f"(d[0]), "+f"(d[1]), "+f"(d[2]), "+f"(d[3])
        : "r"(a[0]), "r"(a[1]), "r"(a[2]), "r"(a[3]), "r"(b0), "r"(b1));
}

// ---------------------------------------------------------------------------
// Pass 1: tf32 tensor-core conv (3-term hi/lo compensation) + bias + window
// max + group stats. Grid (32 rowgroups, 128 batch), block 256 = 8 warps.
// k-dim reordered to (ky,kx,cin): k-step ks = ky*3+kx, k-rows = 8 cin.
// Warp wid: cols wid*16..+15 (2 n-tiles), all 64 couts (4 m-tiles).
// ---------------------------------------------------------------------------
__global__ __launch_bounds__(256, 2) void conv_pass1(const float* __restrict__ x,
                                                     const float* __restrict__ w,
                                                     const float* __restrict__ bias,
                                                     const float* __restrict__ gnw,
                                                     const float* __restrict__ scale)
{
    extern __shared__ __align__(16) char smem[];
    float*  xhi  = (float*) (smem + XHI_OFF);
    float*  xlo  = (float*) (smem + XLO_OFF);
    float4* wfh  = (float4*)(smem + WFH_OFF);
    float4* wfl  = (float4*)(smem + WFL_OFF);
    float*  bsm  = (float*) (smem + BSM_OFF);
    float*  sgsm = (float*) (smem + SGS_OFF);
    float2* sred = (float2*)(smem + SRED_OFF);

    const int pr = blockIdx.x;
    const int b  = blockIdx.y;
    const int t  = threadIdx.x;

    // ---- weight fragments, k-order (ky,kx,cin): k=ks*8+cin -> w k = cin*9+ks
    for (int e = t; e < 1152; e += 256) {          // e = (ks*4+mt)*32 + lane
        int lane = e & 31, mt = (e >> 5) & 3, ks = e >> 7;
        int co0 = mt * 16 + (lane >> 2);
        int t4  = lane & 3;
        float f0 = w[co0 * 72 + t4 * 9 + ks];
        float f1 = w[(co0 + 8) * 72 + t4 * 9 + ks];
        float f2 = w[co0 * 72 + (t4 + 4) * 9 + ks];
        float f3 = w[(co0 + 8) * 72 + (t4 + 4) * 9 + ks];
        unsigned h0 = f2tf(f0), h1 = f2tf(f1), h2 = f2tf(f2), h3 = f2tf(f3);
        wfh[e] = make_float4(__uint_as_float(h0), __uint_as_float(h1),
                             __uint_as_float(h2), __uint_as_float(h3));
        wfl[e] = make_float4(
            __uint_as_float(f2tf(f0 - __uint_as_float(h0))),
            __uint_as_float(f2tf(f1 - __uint_as_float(h1))),
            __uint_as_float(f2tf(f2 - __uint_as_float(h2))),
            __uint_as_float(f2tf(f3 - __uint_as_float(h3))));
    }
    if (t < 64) {
        bsm[t]  = bias[t];
        sgsm[t] = (gnw[t] * scale[t] < 0.f) ? -1.f : 1.f;
    }

    // ---- x tile: separate hi/lo float arrays, rows h0..h0+5 ----
    const int h0 = pr * 4;
    for (int i = t; i < CIN * 6 * 32; i += 256) {
        int c4  = i & 31;
        int rr  = (i >> 5) % 6;
        int cin = i / 192;
        int h   = h0 + rr;
        float4 v = make_float4(0.f, 0.f, 0.f, 0.f);
        if (h < HIN)
            v = *(const float4*)&x[(((size_t)b * CIN + cin) * HIN + h) * WIN + c4 * 4];
        int base = cin * CINSTRIDE + rr * XROW + c4 * 4;
        const float* vp = (const float*)&v;
        float4 hv, lv;
        float* hp = (float*)&hv;
        float* lp = (float*)&lv;
#pragma unroll
        for (int e = 0; e < 4; e++) {
            unsigned hb = f2tf(vp[e]);
            hp[e] = __uint_as_float(hb);
            lp[e] = __uint_as_float(f2tf(vp[e] - __uint_as_float(hb)));
        }
        *(float4*)&xhi[base] = hv;
        *(float4*)&xlo[base] = lv;
    }
    if (t < CIN * 6) {                              // zero pad cols 128..131
        int rr = t % 6, cin = t / 6;
        int base = cin * CINSTRIDE + rr * XROW + 128;
        *(float4*)&xhi[base] = make_float4(0.f, 0.f, 0.f, 0.f);
        *(float4*)&xlo[base] = make_float4(0.f, 0.f, 0.f, 0.f);
    }
    __syncthreads();

    const int lane = t & 31, wid = t >> 5;
    const int g4 = lane >> 2, t4 = lane & 3;
    const int colbase = wid * 16;
    const int R = (pr == 31) ? 2 : 4;

    // per-thread x base pointers (cin = t4 and t4+4)
    const float* xh0 = xhi + t4 * CINSTRIDE + colbase + g4;
    const float* xh1 = xh0 + 4 * CINSTRIDE;
    const float* xl0 = xlo + t4 * CINSTRIDE + colbase + g4;
    const float* xl1 = xl0 + 4 * CINSTRIDE;

    float s8[8], q8[8], wmax[8][2];
#pragma unroll
    for (int i = 0; i < 8; i++) {
        s8[i] = 0.f; q8[i] = 0.f;
        wmax[i][0] = -1e30f; wmax[i][1] = -1e30f;
    }

#pragma unroll 1
    for (int r = 0; r < R; r++) {
        float acc[4][2][4];
#pragma unroll
        for (int mt = 0; mt < 4; mt++)
#pragma unroll
            for (int nt = 0; nt < 2; nt++)
#pragma unroll
                for (int e = 0; e < 4; e++) acc[mt][nt][e] = 0.f;

#pragma unroll 1
        for (int ky = 0; ky < 3; ky++) {
            int rowoff = (r + ky) * XROW;
#pragma unroll
            for (int kx = 0; kx < 3; kx++) {
                int ib = rowoff + kx;
                unsigned bh00 = __float_as_uint(xh0[ib]);
                unsigned bh10 = __float_as_uint(xh1[ib]);
                unsigned bh01 = __float_as_uint(xh0[ib + 8]);
                unsigned bh11 = __float_as_uint(xh1[ib + 8]);
                unsigned bl00 = __float_as_uint(xl0[ib]);
                unsigned bl10 = __float_as_uint(xl1[ib]);
                unsigned bl01 = __float_as_uint(xl0[ib + 8]);
                unsigned bl11 = __float_as_uint(xl1[ib + 8]);
                int wb = (ky * 3 + kx) * 128 + lane;
#pragma unroll
                for (int mt = 0; mt < 4; mt++) {
                    float4 ah4 = wfh[wb + mt * 32];
                    float4 al4 = wfl[wb + mt * 32];
                    unsigned ah[4] = {__float_as_uint(ah4.x), __float_as_uint(ah4.y),
                                      __float_as_uint(ah4.z), __float_as_uint(ah4.w)};
                    unsigned al[4] = {__float_as_uint(al4.x), __float_as_uint(al4.y),
                                      __float_as_uint(al4.z), __float_as_uint(al4.w)};
                    mma8(acc[mt][0], ah, bh00, bh10);
                    mma8(acc[mt][0], ah, bl00, bl10);
                    mma8(acc[mt][0], al, bh00, bh10);
                    mma8(acc[mt][1], ah, bh01, bh11);
                    mma8(acc[mt][1], ah, bl01, bl11);
                    mma8(acc[mt][1], al, bh01, bh11);
                }
            }
        }

        // epilogue row r: bias, stats, sign-adjusted window max
#pragma unroll
        for (int mt = 0; mt < 4; mt++) {
#pragma unroll
            for (int nt = 0; nt < 2; nt++) {
                int col0 = colbase + nt * 8 + 2 * t4;
                bool ok0 = (col0 < 126), ok1 = (col0 + 1 < 126);
#pragma unroll
                for (int cr = 0; cr < 2; cr++) {
                    int co = mt * 16 + g4 + cr * 8;
                    float bb = bsm[co], sg = sgsm[co];
                    float va = acc[mt][nt][cr * 2 + 0] + bb;
                    float vb = acc[mt][nt][cr * 2 + 1] + bb;
                    int si = mt * 2 + cr;
                    if (ok0) { s8[si] += va; q8[si] += va * va; }
                    if (ok1) { s8[si] += vb; q8[si] += vb * vb; }
                    float pm = fmaxf(sg * va, sg * vb);
                    float po = __shfl_xor_sync(0xffffffffu, pm, 1);
                    pm = fmaxf(pm, po);
                    wmax[si][nt] = fmaxf(wmax[si][nt], pm);
                }
            }
        }
    }

    // pooled window writes
    if (pr < 31 && (lane & 1) == 0) {
#pragma unroll
        for (int mt = 0; mt < 4; mt++)
#pragma unroll
            for (int cr = 0; cr < 2; cr++)
#pragma unroll
                for (int nt = 0; nt < 2; nt++) {
                    int pw = wid * 4 + nt * 2 + (t4 >> 1);
                    if (pw < 31) {
                        int co = mt * 16 + g4 + cr * 8;
                        size_t o = (((size_t)b * COUT + co) * PHN + pr) * PWN + pw;
                        g_sext[o] = wmax[mt * 2 + cr][nt];
                    }
                }
    }

    // stats: reduce over t4 lanes (same co), stage per (co, warp), fold
#pragma unroll
    for (int i = 0; i < 8; i++) {
        s8[i] += __shfl_xor_sync(0xffffffffu, s8[i], 1);
        s8[i] += __shfl_xor_sync(0xffffffffu, s8[i], 2);
        q8[i] += __shfl_xor_sync(0xffffffffu, q8[i], 1);
        q8[i] += __shfl_xor_sync(0xffffffffu, q8[i], 2);
    }
    if (t4 == 0) {
#pragma unroll
        for (int mt = 0; mt < 4; mt++)
#pragma unroll
            for (int cr = 0; cr < 2; cr++) {
                int co = mt * 16 + g4 + cr * 8;
                sred[co * 8 + wid] = make_float2(s8[mt * 2 + cr], q8[mt * 2 + cr]);
            }
    }
    __syncthreads();
    if (t < NG) {
        float s = 0.f, q = 0.f;
        for (int c = 0; c < 4; c++)
            for (int w8 = 0; w8 < 8; w8++) {
                float2 p = sred[(t * 4 + c) * 8 + w8];
                s += p.x; q += p.y;
            }
        g_partial[(pr * NB + b) * NG + t] = make_float2(s, q);
    }
}

// ---------------------------------------------------------------------------
__global__ void stats_pass2()
{
    int idx = blockIdx.x * 256 + threadIdx.x;
    if (idx >= NB * NG) return;
    float s = 0.f, q = 0.f;
    for (int pr = 0; pr < 32; pr++) {
        float2 p = g_partial[pr * (NB * NG) + idx];
        s += p.x; q += p.y;
    }
    const float inv = 1.f / (float)(CPG * HO * WO);
    float mean = s * inv;
    float var  = q * inv - mean * mean;
    g_stats[idx] = make_float2(mean, rsqrtf(var + 1e-5f));
}

// ---------------------------------------------------------------------------
__global__ void apply_pass3(const float* __restrict__ gnw,
                            const float* __restrict__ gnb,
                            const float* __restrict__ scale,
                            float* __restrict__ out, int n)
{
    int idx = blockIdx.x * 256 + threadIdx.x;
    if (idx >= n) return;
    int tmp = idx / PWN;
    tmp /= PHN;
    int c = tmp % COUT;
    int b = tmp / COUT;

    float2 st = g_stats[b * NG + (c >> 2)];
    float gw = gnw[c], sc = scale[c];
    float A  = st.y * gw * sc;
    float Bt = (gnb[c] - st.x * st.y * gw) * sc;

    float v = fmaf(fabsf(A), g_sext[idx], Bt);
    out[idx] = fminf(fmaxf(v, 0.f), 1.f);
}

// ---------------------------------------------------------------------------
extern "C" void kernel_launch(void* const* d_in, const int* in_sizes, int n_in,
                              void* d_out, int out_size)
{
    const float* x     = (const float*)d_in[0];
    const float* w     = (const float*)d_in[1];
    const float* bias  = (const float*)d_in[2];
    const float* gnw   = (const float*)d_in[3];
    const float* gnb   = (const float*)d_in[4];
    const float* scale = (const float*)d_in[5];
    float* out = (float*)d_out;

    cudaFuncSetAttribute(conv_pass1, cudaFuncAttributeMaxDynamicSharedMemorySize,
                         SMEM_TOTAL);
    dim3 g1(32, NB);
    conv_pass1<<<g1, 256, SMEM_TOTAL>>>(x, w, bias, gnw, scale);
    stats_pass2<<<(NB * NG + 255) / 256, 256>>>();
    int n = NB * COUT * PHN * PWN;
    apply_pass3<<<(n + 255) / 256, 256>>>(gnw, gnb, scale, out, n);
}

// round 14
// speedup vs baseline: 1.7797x; 1.2809x over previous
#include <cuda_runtime.h>

#define NB    128
#define CIN   8
#define HIN   128
#define WIN   128
#define COUT  64
#define HO    126
#define WO    126
#define PHN   31
#define PWN   31
#define NG    16
#define CPG   4

__device__ float  g_sext[(size_t)NB * COUT * PHN * PWN];
__device__ float2 g_partial[32 * NB * NG];
__device__ float2 g_stats[NB * NG];

// ---- smem layout (bytes). XROW=132 floats -> cin stride 792 ≡ 24 (mod 32)
// banks for B-frag lanes: {g4, 24+g4, 16+g4, 8+g4} -> conflict-free LDS.32.
#define XROW      132
#define CINSTRIDE 792              // 6*132 floats
#define XHI_OFF   0                // float[8*792] = 25344 B
#define XLO_OFF   25344            // float[8*792]
#define WFH_OFF   50688            // float4[9*4*32] = 18432 B
#define BSM_OFF   69120            // float[64]
#define SGS_OFF   69376            // float[64]
#define SRED_OFF  69632            // float2[64*8] = 4096 B
#define SMEM_TOTAL 73728

__device__ __forceinline__ unsigned f2tf(float f) {
    unsigned u; asm("cvt.rna.tf32.f32 %0, %1;" : "=r"(u) : "f"(f)); return u;
}
__device__ __forceinline__ void mma8(float* d, const unsigned* a, unsigned b0, unsigned b1) {
    asm("mma.sync.aligned.m16n8k8.row.col.f32.tf32.tf32.f32 "
        "{%0,%1,%2,%3}, {%4,%5,%6,%7}, {%8,%9}, {%0,%1,%2,%3};"
        : "+f"(d[0]), "+f"(d[1]), "+f"(d[2]), "+f"(d[3])
        : "r"(a[0]), "r"(a[1]), "r"(a[2]), "r"(a[3]), "r"(b0), "r"(b1));
}

// ---------------------------------------------------------------------------
// Pass 1: tf32 tensor-core conv, 2-term x-compensation:
//   w_tf32 * x_hi + w_tf32 * x_lo  (= w_tf32 * x; error = (w - w_tf32)*x)
// Grid (32 rowgroups, 128 batch), block 256 = 8 warps.
// k-dim order (ky,kx,cin): k-step ks = ky*3+kx, k-rows = 8 cin.
// Warp wid: cols wid*16..+15 (2 n-tiles), all 64 couts (4 m-tiles).
// ---------------------------------------------------------------------------
__global__ __launch_bounds__(256, 2) void conv_pass1(const float* __restrict__ x,
                                                     const float* __restrict__ w,
                                                     const float* __restrict__ bias,
                                                     const float* __restrict__ gnw,
                                                     const float* __restrict__ scale)
{
    extern __shared__ __align__(16) char smem[];
    float*  xhi  = (float*) (smem + XHI_OFF);
    float*  xlo  = (float*) (smem + XLO_OFF);
    float4* wfh  = (float4*)(smem + WFH_OFF);
    float*  bsm  = (float*) (smem + BSM_OFF);
    float*  sgsm = (float*) (smem + SGS_OFF);
    float2* sred = (float2*)(smem + SRED_OFF);

    const int pr = blockIdx.x;
    const int b  = blockIdx.y;
    const int t  = threadIdx.x;

    // ---- weight fragments (single tf32), k-order (ky,kx,cin) ----
    for (int e = t; e < 1152; e += 256) {          // e = (ks*4+mt)*32 + lane
        int lane = e & 31, mt = (e >> 5) & 3, ks = e >> 7;
        int co0 = mt * 16 + (lane >> 2);
        int t4  = lane & 3;
        wfh[e] = make_float4(
            __uint_as_float(f2tf(w[co0 * 72 + t4 * 9 + ks])),
            __uint_as_float(f2tf(w[(co0 + 8) * 72 + t4 * 9 + ks])),
            __uint_as_float(f2tf(w[co0 * 72 + (t4 + 4) * 9 + ks])),
            __uint_as_float(f2tf(w[(co0 + 8) * 72 + (t4 + 4) * 9 + ks])));
    }
    if (t < 64) {
        bsm[t]  = bias[t];
        sgsm[t] = (gnw[t] * scale[t] < 0.f) ? -1.f : 1.f;
    }

    // ---- x tile: separate hi/lo float arrays, rows h0..h0+5 ----
    const int h0 = pr * 4;
    for (int i = t; i < CIN * 6 * 32; i += 256) {
        int c4  = i & 31;
        int rr  = (i >> 5) % 6;
        int cin = i / 192;
        int h   = h0 + rr;
        float4 v = make_float4(0.f, 0.f, 0.f, 0.f);
        if (h < HIN)
            v = *(const float4*)&x[(((size_t)b * CIN + cin) * HIN + h) * WIN + c4 * 4];
        int base = cin * CINSTRIDE + rr * XROW + c4 * 4;
        const float* vp = (const float*)&v;
        float4 hv, lv;
        float* hp = (float*)&hv;
        float* lp = (float*)&lv;
#pragma unroll
        for (int e = 0; e < 4; e++) {
            unsigned hb = f2tf(vp[e]);
            hp[e] = __uint_as_float(hb);
            lp[e] = __uint_as_float(f2tf(vp[e] - __uint_as_float(hb)));
        }
        *(float4*)&xhi[base] = hv;
        *(float4*)&xlo[base] = lv;
    }
    if (t < CIN * 6) {                              // zero pad cols 128..131
        int rr = t % 6, cin = t / 6;
        int base = cin * CINSTRIDE + rr * XROW + 128;
        *(float4*)&xhi[base] = make_float4(0.f, 0.f, 0.f, 0.f);
        *(float4*)&xlo[base] = make_float4(0.f, 0.f, 0.f, 0.f);
    }
    __syncthreads();

    const int lane = t & 31, wid = t >> 5;
    const int g4 = lane >> 2, t4 = lane & 3;
    const int colbase = wid * 16;
    const int R = (pr == 31) ? 2 : 4;

    // per-thread x base pointers (cin = t4 and t4+4)
    const float* xh0 = xhi + t4 * CINSTRIDE + colbase + g4;
    const float* xh1 = xh0 + 4 * CINSTRIDE;
    const float* xl0 = xlo + t4 * CINSTRIDE + colbase + g4;
    const float* xl1 = xl0 + 4 * CINSTRIDE;

    float s8[8], q8[8], wmax[8][2];
#pragma unroll
    for (int i = 0; i < 8; i++) {
        s8[i] = 0.f; q8[i] = 0.f;
        wmax[i][0] = -1e30f; wmax[i][1] = -1e30f;
    }

#pragma unroll 1
    for (int r = 0; r < R; r++) {
        float acc[4][2][4];
#pragma unroll
        for (int mt = 0; mt < 4; mt++)
#pragma unroll
            for (int nt = 0; nt < 2; nt++)
#pragma unroll
                for (int e = 0; e < 4; e++) acc[mt][nt][e] = 0.f;

#pragma unroll 1
        for (int ky = 0; ky < 3; ky++) {
            int rowoff = (r + ky) * XROW;
#pragma unroll
            for (int kx = 0; kx < 3; kx++) {
                int ib = rowoff + kx;
                unsigned bh00 = __float_as_uint(xh0[ib]);
                unsigned bh10 = __float_as_uint(xh1[ib]);
                unsigned bh01 = __float_as_uint(xh0[ib + 8]);
                unsigned bh11 = __float_as_uint(xh1[ib + 8]);
                unsigned bl00 = __float_as_uint(xl0[ib]);
                unsigned bl10 = __float_as_uint(xl1[ib]);
                unsigned bl01 = __float_as_uint(xl0[ib + 8]);
                unsigned bl11 = __float_as_uint(xl1[ib + 8]);
                int wb = (ky * 3 + kx) * 128 + lane;
#pragma unroll
                for (int mt = 0; mt < 4; mt++) {
                    float4 ah4 = wfh[wb + mt * 32];
                    unsigned ah[4] = {__float_as_uint(ah4.x), __float_as_uint(ah4.y),
                                      __float_as_uint(ah4.z), __float_as_uint(ah4.w)};
                    mma8(acc[mt][0], ah, bh00, bh10);
                    mma8(acc[mt][0], ah, bl00, bl10);
                    mma8(acc[mt][1], ah, bh01, bh11);
                    mma8(acc[mt][1], ah, bl01, bl11);
                }
            }
        }

        // epilogue row r: bias, stats, sign-adjusted window max
#pragma unroll
        for (int mt = 0; mt < 4; mt++) {
#pragma unroll
            for (int nt = 0; nt < 2; nt++) {
                int col0 = colbase + nt * 8 + 2 * t4;
                bool ok0 = (col0 < 126), ok1 = (col0 + 1 < 126);
#pragma unroll
                for (int cr = 0; cr < 2; cr++) {
                    int co = mt * 16 + g4 + cr * 8;
                    float bb = bsm[co], sg = sgsm[co];
                    float va = acc[mt][nt][cr * 2 + 0] + bb;
                    float vb = acc[mt][nt][cr * 2 + 1] + bb;
                    int si = mt * 2 + cr;
                    if (ok0) { s8[si] += va; q8[si] += va * va; }
                    if (ok1) { s8[si] += vb; q8[si] += vb * vb; }
                    float pm = fmaxf(sg * va, sg * vb);
                    float po = __shfl_xor_sync(0xffffffffu, pm, 1);
                    pm = fmaxf(pm, po);
                    wmax[si][nt] = fmaxf(wmax[si][nt], pm);
                }
            }
        }
    }

    // pooled window writes
    if (pr < 31 && (lane & 1) == 0) {
#pragma unroll
        for (int mt = 0; mt < 4; mt++)
#pragma unroll
            for (int cr = 0; cr < 2; cr++)
#pragma unroll
                for (int nt = 0; nt < 2; nt++) {
                    int pw = wid * 4 + nt * 2 + (t4 >> 1);
                    if (pw < 31) {
                        int co = mt * 16 + g4 + cr * 8;
                        size_t o = (((size_t)b * COUT + co) * PHN + pr) * PWN + pw;
                        g_sext[o] = wmax[mt * 2 + cr][nt];
                    }
                }
    }

    // stats: reduce over t4 lanes (same co), stage per (co, warp), fold
#pragma unroll
    for (int i = 0; i < 8; i++) {
        s8[i] += __shfl_xor_sync(0xffffffffu, s8[i], 1);
        s8[i] += __shfl_xor_sync(0xffffffffu, s8[i], 2);
        q8[i] += __shfl_xor_sync(0xffffffffu, q8[i], 1);
        q8[i] += __shfl_xor_sync(0xffffffffu, q8[i], 2);
    }
    if (t4 == 0) {
#pragma unroll
        for (int mt = 0; mt < 4; mt++)
#pragma unroll
            for (int cr = 0; cr < 2; cr++) {
                int co = mt * 16 + g4 + cr * 8;
                sred[co * 8 + wid] = make_float2(s8[mt * 2 + cr], q8[mt * 2 + cr]);
            }
    }
    __syncthreads();
    if (t < NG) {
        float s = 0.f, q = 0.f;
        for (int c = 0; c < 4; c++)
            for (int w8 = 0; w8 < 8; w8++) {
                float2 p = sred[(t * 4 + c) * 8 + w8];
                s += p.x; q += p.y;
            }
        g_partial[(pr * NB + b) * NG + t] = make_float2(s, q);
    }
}

// ---------------------------------------------------------------------------
__global__ void stats_pass2()
{
    int idx = blockIdx.x * 256 + threadIdx.x;
    if (idx >= NB * NG) return;
    float s = 0.f, q = 0.f;
    for (int pr = 0; pr < 32; pr++) {
        float2 p = g_partial[pr * (NB * NG) + idx];
        s += p.x; q += p.y;
    }
    const float inv = 1.f / (float)(CPG * HO * WO);
    float mean = s * inv;
    float var  = q * inv - mean * mean;
    g_stats[idx] = make_float2(mean, rsqrtf(var + 1e-5f));
}

// ---------------------------------------------------------------------------
__global__ void apply_pass3(const float* __restrict__ gnw,
                            const float* __restrict__ gnb,
                            const float* __restrict__ scale,
                            float* __restrict__ out, int n)
{
    int idx = blockIdx.x * 256 + threadIdx.x;
    if (idx >= n) return;
    int tmp = idx / PWN;
    tmp /= PHN;
    int c = tmp % COUT;
    int b = tmp / COUT;

    float2 st = g_stats[b * NG + (c >> 2)];
    float gw = gnw[c], sc = scale[c];
    float A  = st.y * gw * sc;
    float Bt = (gnb[c] - st.x * st.y * gw) * sc;

    float v = fmaf(fabsf(A), g_sext[idx], Bt);
    out[idx] = fminf(fmaxf(v, 0.f), 1.f);
}

// ---------------------------------------------------------------------------
extern "C" void kernel_launch(void* const* d_in, const int* in_sizes, int n_in,
                              void* d_out, int out_size)
{
    const float* x     = (const float*)d_in[0];
    const float* w     = (const float*)d_in[1];
    const float* bias  = (const float*)d_in[2];
    const float* gnw   = (const float*)d_in[3];
    const float* gnb   = (const float*)d_in[4];
    const float* scale = (const float*)d_in[5];
    float* out = (float*)d_out;

    cudaFuncSetAttribute(conv_pass1, cudaFuncAttributeMaxDynamicSharedMemorySize,
                         SMEM_TOTAL);
    dim3 g1(32, NB);
    conv_pass1<<<g1, 256, SMEM_TOTAL>>>(x, w, bias, gnw, scale);
    stats_pass2<<<(NB * NG + 255) / 256, 256>>>();
    int n = NB * COUT * PHN * PWN;
    apply_pass3<<<(n + 255) / 256, 256>>>(gnw, gnb, scale, out, n);
}

// round 15
// speedup vs baseline: 2.1215x; 1.1921x over previous
#include <cuda_runtime.h>

#define NB    128
#define CIN   8
#define HIN   128
#define WIN   128
#define COUT  64
#define HO    126
#define WO    126
#define PHN   31
#define PWN   31
#define NG    16
#define CPG   4

__device__ float  g_sext[(size_t)NB * COUT * PHN * PWN];
__device__ float2 g_partial[32 * NB * NG];
__device__ float2 g_stats[NB * NG];

// ---- smem layout (bytes). XROW=132 floats -> cin stride 792 ≡ 24 (mod 32)
// banks for B-frag lanes: {g4, 24+g4, 16+g4, 8+g4} -> conflict-free LDS.32.
#define XROW      132
#define CINSTRIDE 792              // 6*132 floats
#define XHI_OFF   0                // float[8*792] = 25344 B (tf32-rounded x)
#define WFH_OFF   25344            // float4[9*4*32] = 18432 B
#define BSM_OFF   43776            // float[64]
#define SGS_OFF   44032            // float[64]
#define SRED_OFF  44288            // float2[64*8] = 4096 B
#define SMEM_TOTAL 48384

__device__ __forceinline__ unsigned f2tf(float f) {
    unsigned u; asm("cvt.rna.tf32.f32 %0, %1;" : "=r"(u) : "f"(f)); return u;
}
__device__ __forceinline__ void mma8(float* d, const unsigned* a, unsigned b0, unsigned b1) {
    asm("mma.sync.aligned.m16n8k8.row.col.f32.tf32.tf32.f32 "
        "{%0,%1,%2,%3}, {%4,%5,%6,%7}, {%8,%9}, {%0,%1,%2,%3};"
        : "+f"(d[0]), "+f"(d[1]), "+f"(d[2]), "+f"(d[3])
        : "r"(a[0]), "r"(a[1]), "r"(a[2]), "r"(a[3]), "r"(b0), "r"(b1));
}

// ---------------------------------------------------------------------------
// Pass 1: pure tf32 tensor-core conv (single term; rel err ~1e-4 << 1e-3)
// Grid (32 rowgroups, 128 batch), block 256 = 8 warps.
// k-dim order (ky,kx,cin): k-step ks = ky*3+kx, k-rows = 8 cin.
// Warp wid: cols wid*16..+15 (2 n-tiles), all 64 couts (4 m-tiles).
// ---------------------------------------------------------------------------
__global__ __launch_bounds__(256, 2) void conv_pass1(const float* __restrict__ x,
                                                     const float* __restrict__ w,
                                                     const float* __restrict__ bias,
                                                     const float* __restrict__ gnw,
                                                     const float* __restrict__ scale)
{
    extern __shared__ __align__(16) char smem[];
    float*  xhi  = (float*) (smem + XHI_OFF);
    float4* wfh  = (float4*)(smem + WFH_OFF);
    float*  bsm  = (float*) (smem + BSM_OFF);
    float*  sgsm = (float*) (smem + SGS_OFF);
    float2* sred = (float2*)(smem + SRED_OFF);

    const int pr = blockIdx.x;
    const int b  = blockIdx.y;
    const int t  = threadIdx.x;

    // ---- weight fragments (tf32), k-order (ky,kx,cin) ----
    for (int e = t; e < 1152; e += 256) {          // e = (ks*4+mt)*32 + lane
        int lane = e & 31, mt = (e >> 5) & 3, ks = e >> 7;
        int co0 = mt * 16 + (lane >> 2);
        int t4  = lane & 3;
        wfh[e] = make_float4(
            __uint_as_float(f2tf(w[co0 * 72 + t4 * 9 + ks])),
            __uint_as_float(f2tf(w[(co0 + 8) * 72 + t4 * 9 + ks])),
            __uint_as_float(f2tf(w[co0 * 72 + (t4 + 4) * 9 + ks])),
            __uint_as_float(f2tf(w[(co0 + 8) * 72 + (t4 + 4) * 9 + ks])));
    }
    if (t < 64) {
        bsm[t]  = bias[t];
        sgsm[t] = (gnw[t] * scale[t] < 0.f) ? -1.f : 1.f;
    }

    // ---- x tile (tf32-rounded), rows h0..h0+5 ----
    const int h0 = pr * 4;
    for (int i = t; i < CIN * 6 * 32; i += 256) {
        int c4  = i & 31;
        int rr  = (i >> 5) % 6;
        int cin = i / 192;
        int h   = h0 + rr;
        float4 v = make_float4(0.f, 0.f, 0.f, 0.f);
        if (h < HIN)
            v = *(const float4*)&x[(((size_t)b * CIN + cin) * HIN + h) * WIN + c4 * 4];
        int base = cin * CINSTRIDE + rr * XROW + c4 * 4;
        const float* vp = (const float*)&v;
        float4 hv;
        float* hp = (float*)&hv;
#pragma unroll
        for (int e = 0; e < 4; e++)
            hp[e] = __uint_as_float(f2tf(vp[e]));
        *(float4*)&xhi[base] = hv;
    }
    if (t < CIN * 6) {                              // zero pad cols 128..131
        int rr = t % 6, cin = t / 6;
        int base = cin * CINSTRIDE + rr * XROW + 128;
        *(float4*)&xhi[base] = make_float4(0.f, 0.f, 0.f, 0.f);
    }
    __syncthreads();

    const int lane = t & 31, wid = t >> 5;
    const int g4 = lane >> 2, t4 = lane & 3;
    const int colbase = wid * 16;
    const int R = (pr == 31) ? 2 : 4;

    // per-thread x base pointers (cin = t4 and t4+4)
    const float* xh0 = xhi + t4 * CINSTRIDE + colbase + g4;
    const float* xh1 = xh0 + 4 * CINSTRIDE;

    float s8[8], q8[8], wmax[8][2];
#pragma unroll
    for (int i = 0; i < 8; i++) {
        s8[i] = 0.f; q8[i] = 0.f;
        wmax[i][0] = -1e30f; wmax[i][1] = -1e30f;
    }

#pragma unroll 1
    for (int r = 0; r < R; r++) {
        float acc[4][2][4];
#pragma unroll
        for (int mt = 0; mt < 4; mt++)
#pragma unroll
            for (int nt = 0; nt < 2; nt++)
#pragma unroll
                for (int e = 0; e < 4; e++) acc[mt][nt][e] = 0.f;

#pragma unroll 1
        for (int ky = 0; ky < 3; ky++) {
            int rowoff = (r + ky) * XROW;
#pragma unroll
            for (int kx = 0; kx < 3; kx++) {
                int ib = rowoff + kx;
                unsigned bh00 = __float_as_uint(xh0[ib]);
                unsigned bh10 = __float_as_uint(xh1[ib]);
                unsigned bh01 = __float_as_uint(xh0[ib + 8]);
                unsigned bh11 = __float_as_uint(xh1[ib + 8]);
                int wb = (ky * 3 + kx) * 128 + lane;
#pragma unroll
                for (int mt = 0; mt < 4; mt++) {
                    float4 ah4 = wfh[wb + mt * 32];
                    unsigned ah[4] = {__float_as_uint(ah4.x), __float_as_uint(ah4.y),
                                      __float_as_uint(ah4.z), __float_as_uint(ah4.w)};
                    mma8(acc[mt][0], ah, bh00, bh10);
                    mma8(acc[mt][1], ah, bh01, bh11);
                }
            }
        }

        // epilogue row r: bias, stats, sign-adjusted window max
#pragma unroll
        for (int mt = 0; mt < 4; mt++) {
#pragma unroll
            for (int nt = 0; nt < 2; nt++) {
                int col0 = colbase + nt * 8 + 2 * t4;
                bool ok0 = (col0 < 126), ok1 = (col0 + 1 < 126);
#pragma unroll
                for (int cr = 0; cr < 2; cr++) {
                    int co = mt * 16 + g4 + cr * 8;
                    float bb = bsm[co], sg = sgsm[co];
                    float va = acc[mt][nt][cr * 2 + 0] + bb;
                    float vb = acc[mt][nt][cr * 2 + 1] + bb;
                    int si = mt * 2 + cr;
                    if (ok0) { s8[si] += va; q8[si] += va * va; }
                    if (ok1) { s8[si] += vb; q8[si] += vb * vb; }
                    float pm = fmaxf(sg * va, sg * vb);
                    float po = __shfl_xor_sync(0xffffffffu, pm, 1);
                    pm = fmaxf(pm, po);
                    wmax[si][nt] = fmaxf(wmax[si][nt], pm);
                }
            }
        }
    }

    // pooled window writes
    if (pr < 31 && (lane & 1) == 0) {
#pragma unroll
        for (int mt = 0; mt < 4; mt++)
#pragma unroll
            for (int cr = 0; cr < 2; cr++)
#pragma unroll
                for (int nt = 0; nt < 2; nt++) {
                    int pw = wid * 4 + nt * 2 + (t4 >> 1);
                    if (pw < 31) {
                        int co = mt * 16 + g4 + cr * 8;
                        size_t o = (((size_t)b * COUT + co) * PHN + pr) * PWN + pw;
                        g_sext[o] = wmax[mt * 2 + cr][nt];
                    }
                }
    }

    // stats: reduce over t4 lanes (same co), stage per (co, warp), fold
#pragma unroll
    for (int i = 0; i < 8; i++) {
        s8[i] += __shfl_xor_sync(0xffffffffu, s8[i], 1);
        s8[i] += __shfl_xor_sync(0xffffffffu, s8[i], 2);
        q8[i] += __shfl_xor_sync(0xffffffffu, q8[i], 1);
        q8[i] += __shfl_xor_sync(0xffffffffu, q8[i], 2);
    }
    if (t4 == 0) {
#pragma unroll
        for (int mt = 0; mt < 4; mt++)
#pragma unroll
            for (int cr = 0; cr < 2; cr++) {
                int co = mt * 16 + g4 + cr * 8;
                sred[co * 8 + wid] = make_float2(s8[mt * 2 + cr], q8[mt * 2 + cr]);
            }
    }
    __syncthreads();
    if (t < NG) {
        float s = 0.f, q = 0.f;
        for (int c = 0; c < 4; c++)
            for (int w8 = 0; w8 < 8; w8++) {
                float2 p = sred[(t * 4 + c) * 8 + w8];
                s += p.x; q += p.y;
            }
        g_partial[(pr * NB + b) * NG + t] = make_float2(s, q);
    }
}

// ---------------------------------------------------------------------------
__global__ void stats_pass2()
{
    int idx = blockIdx.x * 256 + threadIdx.x;
    if (idx >= NB * NG) return;
    float s = 0.f, q = 0.f;
    for (int pr = 0; pr < 32; pr++) {
        float2 p = g_partial[pr * (NB * NG) + idx];
        s += p.x; q += p.y;
    }
    const float inv = 1.f / (float)(CPG * HO * WO);
    float mean = s * inv;
    float var  = q * inv - mean * mean;
    g_stats[idx] = make_float2(mean, rsqrtf(var + 1e-5f));
}

// ---------------------------------------------------------------------------
__global__ void apply_pass3(const float* __restrict__ gnw,
                            const float* __restrict__ gnb,
                            const float* __restrict__ scale,
                            float* __restrict__ out, int n)
{
    int idx = blockIdx.x * 256 + threadIdx.x;
    if (idx >= n) return;
    int tmp = idx / PWN;
    tmp /= PHN;
    int c = tmp % COUT;
    int b = tmp / COUT;

    float2 st = g_stats[b * NG + (c >> 2)];
    float gw = gnw[c], sc = scale[c];
    float A  = st.y * gw * sc;
    float Bt = (gnb[c] - st.x * st.y * gw) * sc;

    float v = fmaf(fabsf(A), g_sext[idx], Bt);
    out[idx] = fminf(fmaxf(v, 0.f), 1.f);
}

// ---------------------------------------------------------------------------
extern "C" void kernel_launch(void* const* d_in, const int* in_sizes, int n_in,
                              void* d_out, int out_size)
{
    const float* x     = (const float*)d_in[0];
    const float* w     = (const float*)d_in[1];
    const float* bias  = (const float*)d_in[2];
    const float* gnw   = (const float*)d_in[3];
    const float* gnb   = (const float*)d_in[4];
    const float* scale = (const float*)d_in[5];
    float* out = (float*)d_out;

    cudaFuncSetAttribute(conv_pass1, cudaFuncAttributeMaxDynamicSharedMemorySize,
                         SMEM_TOTAL);
    dim3 g1(32, NB);
    conv_pass1<<<g1, 256, SMEM_TOTAL>>>(x, w, bias, gnw, scale);
    stats_pass2<<<(NB * NG + 255) / 256, 256>>>();
    int n = NB * COUT * PHN * PWN;
    apply_pass3<<<(n + 255) / 256, 256>>>(gnw, gnb, scale, out, n);
}

// round 16
// speedup vs baseline: 2.3868x; 1.1250x over previous
#include <cuda_runtime.h>

#define NB    128
#define CIN   8
#define HIN   128
#define WIN   128
#define COUT  64
#define HO    126
#define WO    126
#define PHN   31
#define PWN   31
#define NG    16
#define CPG   4

__device__ float  g_sext[(size_t)NB * COUT * PHN * PWN];
__device__ float2 g_partial[32 * NB * NG];
__device__ float2 g_stats[NB * NG];
__device__ float4 g_wfrag[1152];       // precomputed tf32 A-fragments

// ---- smem layout (bytes). XROW=132 floats -> cin stride 792 ≡ 24 (mod 32)
// banks for B-frag lanes: {g4, 24+g4, 16+g4, 8+g4} -> conflict-free LDS.32.
#define XROW      132
#define CINSTRIDE 792              // 6*132 floats
#define XHI_OFF   0                // float[8*792] = 25344 B (tf32-rounded x)
#define WFH_OFF   25344            // float4[9*4*32] = 18432 B
#define BSM_OFF   43776            // float[64]
#define SGS_OFF   44032            // float[64]
#define SRED_OFF  44288            // float2[64*4] = 2048 B
#define SMEM_TOTAL 46336

__device__ __forceinline__ unsigned f2tf(float f) {
    unsigned u; asm("cvt.rna.tf32.f32 %0, %1;" : "=r"(u) : "f"(f)); return u;
}
__device__ __forceinline__ void mma8(float* d, const unsigned* a, unsigned b0, unsigned b1) {
    asm("mma.sync.aligned.m16n8k8.row.col.f32.tf32.tf32.f32 "
        "{%0,%1,%2,%3}, {%4,%5,%6,%7}, {%8,%9}, {%0,%1,%2,%3};"
        : "+f"(d[0]), "+f"(d[1]), "+f"(d[2]), "+f"(d[3])
        : "r"(a[0]), "r"(a[1]), "r"(a[2]), "r"(a[3]), "r"(b0), "r"(b1));
}

// ---------------------------------------------------------------------------
// Pre-pass: build tf32 A-fragments once. e = (ks*4 + mtg)*32 + lane.
// ---------------------------------------------------------------------------
__global__ void wprep(const float* __restrict__ w)
{
    int e = blockIdx.x * 256 + threadIdx.x;
    if (e >= 1152) return;
    int lane = e & 31, mtg = (e >> 5) & 3, ks = e >> 7;
    int co0 = mtg * 16 + (lane >> 2);
    int t4  = lane & 3;
    g_wfrag[e] = make_float4(
        __uint_as_float(f2tf(w[co0 * 72 + t4 * 9 + ks])),
        __uint_as_float(f2tf(w[(co0 + 8) * 72 + t4 * 9 + ks])),
        __uint_as_float(f2tf(w[co0 * 72 + (t4 + 4) * 9 + ks])),
        __uint_as_float(f2tf(w[(co0 + 8) * 72 + (t4 + 4) * 9 + ks])));
}

// ---------------------------------------------------------------------------
// Pass 1: pure tf32 tensor-core conv. Grid (32 rowgroups, 128 batch), 256 thr.
// 8 warps = 2 cout-halves (ch) x 4 col-groups (cg, 32 cols each).
// Warp: mt=2 (couts ch*32..+31), nt=4 (cols cg*32..+31).
// k-dim order (ky,kx,cin): ks = ky*3+kx, k-rows = 8 cin.
// ---------------------------------------------------------------------------
__global__ __launch_bounds__(256, 2) void conv_pass1(const float* __restrict__ x,
                                                     const float* __restrict__ bias,
                                                     const float* __restrict__ gnw,
                                                     const float* __restrict__ scale)
{
    extern __shared__ __align__(16) char smem[];
    float*  xhi  = (float*) (smem + XHI_OFF);
    float4* wfh  = (float4*)(smem + WFH_OFF);
    float*  bsm  = (float*) (smem + BSM_OFF);
    float*  sgsm = (float*) (smem + SGS_OFF);
    float2* sred = (float2*)(smem + SRED_OFF);

    const int pr = blockIdx.x;
    const int b  = blockIdx.y;
    const int t  = threadIdx.x;

    // ---- weight fragments: coalesced copy from precomputed global ----
    for (int e = t; e < 1152; e += 256)
        wfh[e] = g_wfrag[e];
    if (t < 64) {
        bsm[t]  = bias[t];
        sgsm[t] = (gnw[t] * scale[t] < 0.f) ? -1.f : 1.f;
    }

    // ---- x tile (tf32-rounded), rows h0..h0+5 ----
    const int h0 = pr * 4;
    for (int i = t; i < CIN * 6 * 32; i += 256) {
        int c4  = i & 31;
        int rr  = (i >> 5) % 6;
        int cin = i / 192;
        int h   = h0 + rr;
        float4 v = make_float4(0.f, 0.f, 0.f, 0.f);
        if (h < HIN)
            v = *(const float4*)&x[(((size_t)b * CIN + cin) * HIN + h) * WIN + c4 * 4];
        int base = cin * CINSTRIDE + rr * XROW + c4 * 4;
        const float* vp = (const float*)&v;
        float4 hv;
        float* hp = (float*)&hv;
#pragma unroll
        for (int e = 0; e < 4; e++)
            hp[e] = __uint_as_float(f2tf(vp[e]));
        *(float4*)&xhi[base] = hv;
    }
    if (t < CIN * 6) {                              // zero pad cols 128..131
        int rr = t % 6, cin = t / 6;
        int base = cin * CINSTRIDE + rr * XROW + 128;
        *(float4*)&xhi[base] = make_float4(0.f, 0.f, 0.f, 0.f);
    }
    __syncthreads();

    const int lane = t & 31, wid = t >> 5;
    const int g4 = lane >> 2, t4 = lane & 3;
    const int ch = wid >> 2;                // cout half (0,1)
    const int cg = wid & 3;                 // col group (32 cols each)
    const int colbase = cg * 32;
    const int R = (pr == 31) ? 2 : 4;

    // per-thread x base pointers (cin = t4 and t4+4)
    const float* xh0 = xhi + t4 * CINSTRIDE + colbase + g4;
    const float* xh1 = xh0 + 4 * CINSTRIDE;

    float s4[4], q4[4], wmax[4][4];         // si = mtl*2+cr; nt = 0..3
#pragma unroll
    for (int i = 0; i < 4; i++) {
        s4[i] = 0.f; q4[i] = 0.f;
#pragma unroll
        for (int nt = 0; nt < 4; nt++) wmax[i][nt] = -1e30f;
    }

#pragma unroll 1
    for (int r = 0; r < R; r++) {
        float acc[2][4][4];                 // [mtl][nt][e]
#pragma unroll
        for (int mtl = 0; mtl < 2; mtl++)
#pragma unroll
            for (int nt = 0; nt < 4; nt++)
#pragma unroll
                for (int e = 0; e < 4; e++) acc[mtl][nt][e] = 0.f;

#pragma unroll 1
        for (int ky = 0; ky < 3; ky++) {
            int rowoff = (r + ky) * XROW;
#pragma unroll
            for (int kx = 0; kx < 3; kx++) {
                int ib = rowoff + kx;
                unsigned b0[4], b1[4];
#pragma unroll
                for (int nt = 0; nt < 4; nt++) {
                    b0[nt] = __float_as_uint(xh0[ib + 8 * nt]);
                    b1[nt] = __float_as_uint(xh1[ib + 8 * nt]);
                }
                int wb = (ky * 3 + kx) * 128 + ch * 64 + lane;
#pragma unroll
                for (int mtl = 0; mtl < 2; mtl++) {
                    float4 ah4 = wfh[wb + mtl * 32];
                    unsigned ah[4] = {__float_as_uint(ah4.x), __float_as_uint(ah4.y),
                                      __float_as_uint(ah4.z), __float_as_uint(ah4.w)};
#pragma unroll
                    for (int nt = 0; nt < 4; nt++)
                        mma8(acc[mtl][nt], ah, b0[nt], b1[nt]);
                }
            }
        }

        // epilogue row r: bias, stats, sign-adjusted window max
#pragma unroll
        for (int mtl = 0; mtl < 2; mtl++) {
#pragma unroll
            for (int nt = 0; nt < 4; nt++) {
                int col0 = colbase + nt * 8 + 2 * t4;
                bool ok0 = (col0 < 126), ok1 = (col0 + 1 < 126);
#pragma unroll
                for (int cr = 0; cr < 2; cr++) {
                    int co = ch * 32 + mtl * 16 + g4 + cr * 8;
                    float bb = bsm[co], sg = sgsm[co];
                    float va = acc[mtl][nt][cr * 2 + 0] + bb;
                    float vb = acc[mtl][nt][cr * 2 + 1] + bb;
                    int si = mtl * 2 + cr;
                    if (ok0) { s4[si] += va; q4[si] += va * va; }
                    if (ok1) { s4[si] += vb; q4[si] += vb * vb; }
                    float pm = fmaxf(sg * va, sg * vb);
                    float po = __shfl_xor_sync(0xffffffffu, pm, 1);
                    pm = fmaxf(pm, po);
                    wmax[si][nt] = fmaxf(wmax[si][nt], pm);
                }
            }
        }
    }

    // pooled window writes (this block = pool row pr; warp covers 8 windows)
    if (pr < 31 && (lane & 1) == 0) {
#pragma unroll
        for (int mtl = 0; mtl < 2; mtl++)
#pragma unroll
            for (int cr = 0; cr < 2; cr++)
#pragma unroll
                for (int nt = 0; nt < 4; nt++) {
                    int pw = cg * 8 + nt * 2 + (t4 >> 1);
                    if (pw < 31) {
                        int co = ch * 32 + mtl * 16 + g4 + cr * 8;
                        size_t o = (((size_t)b * COUT + co) * PHN + pr) * PWN + pw;
                        g_sext[o] = wmax[mtl * 2 + cr][nt];
                    }
                }
    }

    // stats: reduce over t4 lanes (same co), stage per (co, colgroup), fold
#pragma unroll
    for (int i = 0; i < 4; i++) {
        s4[i] += __shfl_xor_sync(0xffffffffu, s4[i], 1);
        s4[i] += __shfl_xor_sync(0xffffffffu, s4[i], 2);
        q4[i] += __shfl_xor_sync(0xffffffffu, q4[i], 1);
        q4[i] += __shfl_xor_sync(0xffffffffu, q4[i], 2);
    }
    if (t4 == 0) {
#pragma unroll
        for (int mtl = 0; mtl < 2; mtl++)
#pragma unroll
            for (int cr = 0; cr < 2; cr++) {
                int co = ch * 32 + mtl * 16 + g4 + cr * 8;
                sred[co * 4 + cg] = make_float2(s4[mtl * 2 + cr], q4[mtl * 2 + cr]);
            }
    }
    __syncthreads();
    if (t < NG) {
        float s = 0.f, q = 0.f;
        for (int c = 0; c < 4; c++)
            for (int cg2 = 0; cg2 < 4; cg2++) {
                float2 p = sred[(t * 4 + c) * 4 + cg2];
                s += p.x; q += p.y;
            }
        g_partial[(pr * NB + b) * NG + t] = make_float2(s, q);
    }
}

// ---------------------------------------------------------------------------
__global__ void stats_pass2()
{
    int idx = blockIdx.x * 256 + threadIdx.x;
    if (idx >= NB * NG) return;
    float s = 0.f, q = 0.f;
    for (int pr = 0; pr < 32; pr++) {
        float2 p = g_partial[pr * (NB * NG) + idx];
        s += p.x; q += p.y;
    }
    const float inv = 1.f / (float)(CPG * HO * WO);
    float mean = s * inv;
    float var  = q * inv - mean * mean;
    g_stats[idx] = make_float2(mean, rsqrtf(var + 1e-5f));
}

// ---------------------------------------------------------------------------
__global__ void apply_pass3(const float* __restrict__ gnw,
                            const float* __restrict__ gnb,
                            const float* __restrict__ scale,
                            float* __restrict__ out, int n)
{
    int idx = blockIdx.x * 256 + threadIdx.x;
    if (idx >= n) return;
    int tmp = idx / PWN;
    tmp /= PHN;
    int c = tmp % COUT;
    int b = tmp / COUT;

    float2 st = g_stats[b * NG + (c >> 2)];
    float gw = gnw[c], sc = scale[c];
    float A  = st.y * gw * sc;
    float Bt = (gnb[c] - st.x * st.y * gw) * sc;

    float v = fmaf(fabsf(A), g_sext[idx], Bt);
    out[idx] = fminf(fmaxf(v, 0.f), 1.f);
}

// ---------------------------------------------------------------------------
extern "C" void kernel_launch(void* const* d_in, const int* in_sizes, int n_in,
                              void* d_out, int out_size)
{
    const float* x     = (const float*)d_in[0];
    const float* w     = (const float*)d_in[1];
    const float* bias  = (const float*)d_in[2];
    const float* gnw   = (const float*)d_in[3];
    const float* gnb   = (const float*)d_in[4];
    const float* scale = (const float*)d_in[5];
    float* out = (float*)d_out;

    cudaFuncSetAttribute(conv_pass1, cudaFuncAttributeMaxDynamicSharedMemorySize,
                         SMEM_TOTAL);
    wprep<<<5, 256>>>(w);
    dim3 g1(32, NB);
    conv_pass1<<<g1, 256, SMEM_TOTAL>>>(x, bias, gnw, scale);
    stats_pass2<<<(NB * NG + 255) / 256, 256>>>();
    int n = NB * COUT * PHN * PWN;
    apply_pass3<<<(n + 255) / 256, 256>>>(gnw, gnb, scale, out, n);
}

// round 17
// speedup vs baseline: 2.5522x; 1.0693x over previous
#include <cuda_runtime.h>

#define NB    128
#define CIN   8
#define HIN   128
#define WIN   128
#define COUT  64
#define HO    126
#define WO    126
#define PHN   31
#define PWN   31
#define NG    16
#define CPG   4

__device__ float  g_sext[(size_t)NB * COUT * PHN * PWN];
__device__ float2 g_partial[32 * NB * NG];
__device__ float2 g_coef[NB * COUT];   // per (b,c): (|A|, Bt)
__device__ float4 g_wfrag[1152];       // precomputed tf32 A-fragments

// ---- smem layout (bytes). XROW=132 floats -> cin stride 792 ≡ 24 (mod 32)
// banks for B-frag lanes: {g4, 24+g4, 16+g4, 8+g4} -> conflict-free LDS.32.
#define XROW      132
#define CINSTRIDE 792              // 6*132 floats
#define XHI_OFF   0                // float[8*792] = 25344 B (tf32-rounded x)
#define WFH_OFF   25344            // float4[9*4*32] = 18432 B
#define BSM_OFF   43776            // float[64]
#define SGS_OFF   44032            // float[64]
#define SRED_OFF  44288            // float2[64*4] = 2048 B
#define SMEM_TOTAL 46336

__device__ __forceinline__ unsigned f2tf(float f) {
    unsigned u; asm("cvt.rna.tf32.f32 %0, %1;" : "=r"(u) : "f"(f)); return u;
}
__device__ __forceinline__ void mma8(float* d, const unsigned* a, unsigned b0, unsigned b1) {
    asm("mma.sync.aligned.m16n8k8.row.col.f32.tf32.tf32.f32 "
        "{%0,%1,%2,%3}, {%4,%5,%6,%7}, {%8,%9}, {%0,%1,%2,%3};"
        : "+f"(d[0]), "+f"(d[1]), "+f"(d[2]), "+f"(d[3])
        : "r"(a[0]), "r"(a[1]), "r"(a[2]), "r"(a[3]), "r"(b0), "r"(b1));
}

// ---------------------------------------------------------------------------
// Pre-pass: build tf32 A-fragments once. e = (ks*4 + mtg)*32 + lane.
// ---------------------------------------------------------------------------
__global__ void wprep(const float* __restrict__ w)
{
    int e = blockIdx.x * 256 + threadIdx.x;
    if (e >= 1152) return;
    int lane = e & 31, mtg = (e >> 5) & 3, ks = e >> 7;
    int co0 = mtg * 16 + (lane >> 2);
    int t4  = lane & 3;
    g_wfrag[e] = make_float4(
        __uint_as_float(f2tf(w[co0 * 72 + t4 * 9 + ks])),
        __uint_as_float(f2tf(w[(co0 + 8) * 72 + t4 * 9 + ks])),
        __uint_as_float(f2tf(w[co0 * 72 + (t4 + 4) * 9 + ks])),
        __uint_as_float(f2tf(w[(co0 + 8) * 72 + (t4 + 4) * 9 + ks])));
}

// ---------------------------------------------------------------------------
// Pass 1: pure tf32 tensor-core conv. Grid (32 rowgroups, 128 batch), 256 thr.
// 8 warps = 2 cout-halves (ch) x 4 col-groups (cg, 32 cols each).
// Warp: mt=2 (couts ch*32..+31), nt=4 (cols cg*32..+31).
// k-dim order (ky,kx,cin): ks = ky*3+kx, k-rows = 8 cin.
// ---------------------------------------------------------------------------
__global__ __launch_bounds__(256, 2) void conv_pass1(const float* __restrict__ x,
                                                     const float* __restrict__ bias,
                                                     const float* __restrict__ gnw,
                                                     const float* __restrict__ scale)
{
    extern __shared__ __align__(16) char smem[];
    float*  xhi  = (float*) (smem + XHI_OFF);
    float4* wfh  = (float4*)(smem + WFH_OFF);
    float*  bsm  = (float*) (smem + BSM_OFF);
    float*  sgsm = (float*) (smem + SGS_OFF);
    float2* sred = (float2*)(smem + SRED_OFF);

    const int pr = blockIdx.x;
    const int b  = blockIdx.y;
    const int t  = threadIdx.x;

    // ---- weight fragments: coalesced copy from precomputed global ----
    for (int e = t; e < 1152; e += 256)
        wfh[e] = g_wfrag[e];
    if (t < 64) {
        bsm[t]  = bias[t];
        sgsm[t] = (gnw[t] * scale[t] < 0.f) ? -1.f : 1.f;
    }

    // ---- x tile (tf32-rounded), rows h0..h0+5 ----
    const int h0 = pr * 4;
    for (int i = t; i < CIN * 6 * 32; i += 256) {
        int c4  = i & 31;
        int rr  = (i >> 5) % 6;
        int cin = i / 192;
        int h   = h0 + rr;
        float4 v = make_float4(0.f, 0.f, 0.f, 0.f);
        if (h < HIN)
            v = *(const float4*)&x[(((size_t)b * CIN + cin) * HIN + h) * WIN + c4 * 4];
        int base = cin * CINSTRIDE + rr * XROW + c4 * 4;
        const float* vp = (const float*)&v;
        float4 hv;
        float* hp = (float*)&hv;
#pragma unroll
        for (int e = 0; e < 4; e++)
            hp[e] = __uint_as_float(f2tf(vp[e]));
        *(float4*)&xhi[base] = hv;
    }
    if (t < CIN * 6) {                              // zero pad cols 128..131
        int rr = t % 6, cin = t / 6;
        int base = cin * CINSTRIDE + rr * XROW + 128;
        *(float4*)&xhi[base] = make_float4(0.f, 0.f, 0.f, 0.f);
    }
    __syncthreads();

    const int lane = t & 31, wid = t >> 5;
    const int g4 = lane >> 2, t4 = lane & 3;
    const int ch = wid >> 2;                // cout half (0,1)
    const int cg = wid & 3;                 // col group (32 cols each)
    const int colbase = cg * 32;
    const int R = (pr == 31) ? 2 : 4;

    // per-thread x base pointers (cin = t4 and t4+4)
    const float* xh0 = xhi + t4 * CINSTRIDE + colbase + g4;
    const float* xh1 = xh0 + 4 * CINSTRIDE;

    float s4[4], q4[4], wmax[4][4];         // si = mtl*2+cr; nt = 0..3
#pragma unroll
    for (int i = 0; i < 4; i++) {
        s4[i] = 0.f; q4[i] = 0.f;
#pragma unroll
        for (int nt = 0; nt < 4; nt++) wmax[i][nt] = -1e30f;
    }

#pragma unroll 1
    for (int r = 0; r < R; r++) {
        float acc[2][4][4];                 // [mtl][nt][e]
#pragma unroll
        for (int mtl = 0; mtl < 2; mtl++)
#pragma unroll
            for (int nt = 0; nt < 4; nt++)
#pragma unroll
                for (int e = 0; e < 4; e++) acc[mtl][nt][e] = 0.f;

#pragma unroll 1
        for (int ky = 0; ky < 3; ky++) {
            int rowoff = (r + ky) * XROW;
#pragma unroll
            for (int kx = 0; kx < 3; kx++) {
                int ib = rowoff + kx;
                unsigned b0[4], b1[4];
#pragma unroll
                for (int nt = 0; nt < 4; nt++) {
                    b0[nt] = __float_as_uint(xh0[ib + 8 * nt]);
                    b1[nt] = __float_as_uint(xh1[ib + 8 * nt]);
                }
                int wb = (ky * 3 + kx) * 128 + ch * 64 + lane;
#pragma unroll
                for (int mtl = 0; mtl < 2; mtl++) {
                    float4 ah4 = wfh[wb + mtl * 32];
                    unsigned ah[4] = {__float_as_uint(ah4.x), __float_as_uint(ah4.y),
                                      __float_as_uint(ah4.z), __float_as_uint(ah4.w)};
#pragma unroll
                    for (int nt = 0; nt < 4; nt++)
                        mma8(acc[mtl][nt], ah, b0[nt], b1[nt]);
                }
            }
        }

        // epilogue row r: bias, stats, sign-adjusted window max
#pragma unroll
        for (int mtl = 0; mtl < 2; mtl++) {
#pragma unroll
            for (int nt = 0; nt < 4; nt++) {
                int col0 = colbase + nt * 8 + 2 * t4;
                bool ok0 = (col0 < 126), ok1 = (col0 + 1 < 126);
#pragma unroll
                for (int cr = 0; cr < 2; cr++) {
                    int co = ch * 32 + mtl * 16 + g4 + cr * 8;
                    float bb = bsm[co], sg = sgsm[co];
                    float va = acc[mtl][nt][cr * 2 + 0] + bb;
                    float vb = acc[mtl][nt][cr * 2 + 1] + bb;
                    int si = mtl * 2 + cr;
                    if (ok0) { s4[si] += va; q4[si] += va * va; }
                    if (ok1) { s4[si] += vb; q4[si] += vb * vb; }
                    float pm = fmaxf(sg * va, sg * vb);
                    float po = __shfl_xor_sync(0xffffffffu, pm, 1);
                    pm = fmaxf(pm, po);
                    wmax[si][nt] = fmaxf(wmax[si][nt], pm);
                }
            }
        }
    }

    // pooled window writes (this block = pool row pr; warp covers 8 windows)
    if (pr < 31 && (lane & 1) == 0) {
#pragma unroll
        for (int mtl = 0; mtl < 2; mtl++)
#pragma unroll
            for (int cr = 0; cr < 2; cr++)
#pragma unroll
                for (int nt = 0; nt < 4; nt++) {
                    int pw = cg * 8 + nt * 2 + (t4 >> 1);
                    if (pw < 31) {
                        int co = ch * 32 + mtl * 16 + g4 + cr * 8;
                        size_t o = (((size_t)b * COUT + co) * PHN + pr) * PWN + pw;
                        g_sext[o] = wmax[mtl * 2 + cr][nt];
                    }
                }
    }

    // stats: reduce over t4 lanes (same co), stage per (co, colgroup), fold
#pragma unroll
    for (int i = 0; i < 4; i++) {
        s4[i] += __shfl_xor_sync(0xffffffffu, s4[i], 1);
        s4[i] += __shfl_xor_sync(0xffffffffu, s4[i], 2);
        q4[i] += __shfl_xor_sync(0xffffffffu, q4[i], 1);
        q4[i] += __shfl_xor_sync(0xffffffffu, q4[i], 2);
    }
    if (t4 == 0) {
#pragma unroll
        for (int mtl = 0; mtl < 2; mtl++)
#pragma unroll
            for (int cr = 0; cr < 2; cr++) {
                int co = ch * 32 + mtl * 16 + g4 + cr * 8;
                sred[co * 4 + cg] = make_float2(s4[mtl * 2 + cr], q4[mtl * 2 + cr]);
            }
    }
    __syncthreads();
    if (t < NG) {
        float s = 0.f, q = 0.f;
        for (int c = 0; c < 4; c++)
            for (int cg2 = 0; cg2 < 4; cg2++) {
                float2 p = sred[(t * 4 + c) * 4 + cg2];
                s += p.x; q += p.y;
            }
        g_partial[(pr * NB + b) * NG + t] = make_float2(s, q);
    }
}

// ---------------------------------------------------------------------------
// Pass 2: per (b, c) fold group partials -> coefficient (|A|, Bt).
// ---------------------------------------------------------------------------
__global__ void coef_pass2(const float* __restrict__ gnw,
                           const float* __restrict__ gnb,
                           const float* __restrict__ scale)
{
    int idx = blockIdx.x * 256 + threadIdx.x;   // b*64+c
    if (idx >= NB * COUT) return;
    int c = idx & 63;
    int b = idx >> 6;
    int gi = b * NG + (c >> 2);

    float s = 0.f, q = 0.f;
    for (int pr = 0; pr < 32; pr++) {
        float2 p = g_partial[pr * (NB * NG) + gi];
        s += p.x; q += p.y;
    }
    const float inv = 1.f / (float)(CPG * HO * WO);
    float mean = s * inv;
    float var  = q * inv - mean * mean;
    float rstd = rsqrtf(var + 1e-5f);

    float gw = gnw[c], sc = scale[c];
    float A  = rstd * gw * sc;
    float Bt = (gnb[c] - mean * rstd * gw) * sc;
    g_coef[idx] = make_float2(fabsf(A), Bt);
}

// ---------------------------------------------------------------------------
// Pass 3: float4 over whole array; per element plane = e/961 -> coef.
// ---------------------------------------------------------------------------
__global__ void apply_pass3(float* __restrict__ out, int n4)
{
    int tid = blockIdx.x * 256 + threadIdx.x;
    if (tid >= n4) return;
    float4 v = *((const float4*)g_sext + tid);
    unsigned e0 = (unsigned)tid * 4u;
    float r[4];
    const float* vp = (const float*)&v;
#pragma unroll
    for (int j = 0; j < 4; j++) {
        unsigned p = (e0 + j) / 961u;       // plane = (b*64+c)
        float2 cf = g_coef[p];
        r[j] = fminf(fmaxf(fmaf(cf.x, vp[j], cf.y), 0.f), 1.f);
    }
    *((float4*)out + tid) = make_float4(r[0], r[1], r[2], r[3]);
}

// ---------------------------------------------------------------------------
extern "C" void kernel_launch(void* const* d_in, const int* in_sizes, int n_in,
                              void* d_out, int out_size)
{
    const float* x     = (const float*)d_in[0];
    const float* w     = (const float*)d_in[1];
    const float* bias  = (const float*)d_in[2];
    const float* gnw   = (const float*)d_in[3];
    const float* gnb   = (const float*)d_in[4];
    const float* scale = (const float*)d_in[5];
    float* out = (float*)d_out;

    cudaFuncSetAttribute(conv_pass1, cudaFuncAttributeMaxDynamicSharedMemorySize,
                         SMEM_TOTAL);
    wprep<<<5, 256>>>(w);
    dim3 g1(32, NB);
    conv_pass1<<<g1, 256, SMEM_TOTAL>>>(x, bias, gnw, scale);
    coef_pass2<<<(NB * COUT + 255) / 256, 256>>>(gnw, gnb, scale);
    int n4 = (NB * COUT * PHN * PWN) / 4;   // 7,875,584 / 4 exactly
    apply_pass3<<<(n4 + 255) / 256, 256>>>(out, n4);
}